// round 16
// baseline (speedup 1.0000x reference)
#include <cuda_runtime.h>
#include <cuda.h>
#include <cstdint>
#include <cstddef>

// ---------------- problem constants ----------------
#define TT 16384
#define KK 2048
#define NN 8192
#define EE 8

static constexpr int BM = 128;
static constexpr int BN = 128;
static constexpr int BK = 32;                  // floats per stage row chunk = 128 bytes
static constexpr int STAGES = 4;
static constexpr int KTILES = KK / BK;         // 64

static constexpr int A_STG = BM * 128;         // 16384 B
static constexpr int B_STG = BN * 128;         // 16384 B
static constexpr int SM_FULL  = 0;             // 4 x 8B mbarriers
static constexpr int SM_EMPTY = SM_FULL + STAGES * 8;
static constexpr int SM_A = 1024;
static constexpr int SM_B = SM_A + STAGES * A_STG;
static constexpr int SMEM_TOTAL = SM_B + STAGES * B_STG;   // 132096
static constexpr uint32_t STAGE_TX = (uint32_t)(A_STG + B_STG);

static constexpr int NCT = NN / BN;   // 64 col tiles
static constexpr int MT  = TT / BM;   // 128 row tiles
static constexpr int GM  = 16;        // m-tile group for L2 locality

// ---------------- scratch: tf32-rounded operands ----------------
__device__ float g_xc[(size_t)TT * KK];            // [T][K]
__device__ float g_wt[(size_t)EE * NN * KK];       // [E][N][K]

// ---------------- PTX helpers (base sm_103-safe: no tcgen05) ----------------
__device__ __forceinline__ uint32_t smem_u32(const void* p) {
    uint32_t a;
    asm("{ .reg .u64 t; cvta.to.shared.u64 t, %1; cvt.u32.u64 %0, t; }" : "=r"(a) : "l"(p));
    return a;
}
__device__ __forceinline__ float rna_tf32(float f) {
    uint32_t u; asm("cvt.rna.tf32.f32 %0, %1;" : "=r"(u) : "f"(f));
    return __uint_as_float(u);
}
__device__ __forceinline__ void mbar_init(uint32_t m, uint32_t cnt) {
    asm volatile("mbarrier.init.shared.b64 [%0], %1;" :: "r"(m), "r"(cnt) : "memory");
}
__device__ __forceinline__ void mbar_expect_tx(uint32_t m, uint32_t bytes) {
    asm volatile("mbarrier.arrive.expect_tx.shared.b64 _, [%0], %1;" :: "r"(m), "r"(bytes) : "memory");
}
__device__ __forceinline__ void mbar_arrive(uint32_t m) {
    asm volatile("mbarrier.arrive.shared.b64 _, [%0];" :: "r"(m) : "memory");
}
__device__ __forceinline__ void mbar_wait(uint32_t m, uint32_t parity) {
    asm volatile(
        "{\n\t.reg .pred P;\n\t"
        "WL_%=:\n\t"
        "mbarrier.try_wait.parity.shared.b64 P, [%0], %1, 0x989680;\n\t"
        "@!P bra WL_%=;\n\t}"
        :: "r"(m), "r"(parity) : "memory");
}
__device__ __forceinline__ void tma_ld2d(uint32_t dst, const CUtensorMap* map,
                                         int cx, int cy, uint32_t mbar) {
    asm volatile(
        "cp.async.bulk.tensor.2d.shared::cta.global.tile.mbarrier::complete_tx::bytes "
        "[%0], [%1, {%2, %3}], [%4];"
        :: "r"(dst), "l"(map), "r"(cx), "r"(cy), "r"(mbar) : "memory");
}
__device__ __forceinline__ uint32_t lds32(uint32_t addr) {
    uint32_t v;
    asm volatile("ld.shared.b32 %0, [%1];" : "=r"(v) : "r"(addr));
    return v;
}
// D += A*B : m16n8k8 tf32 (available on base target, sm_80+)
__device__ __forceinline__ void mma8(float c[4], const uint32_t a[4], const uint32_t b[2]) {
    asm volatile(
        "mma.sync.aligned.m16n8k8.row.col.f32.tf32.tf32.f32 "
        "{%0,%1,%2,%3}, {%4,%5,%6,%7}, {%8,%9}, {%0,%1,%2,%3};"
        : "+f"(c[0]), "+f"(c[1]), "+f"(c[2]), "+f"(c[3])
        : "r"(a[0]), "r"(a[1]), "r"(a[2]), "r"(a[3]), "r"(b[0]), "r"(b[1]));
}

// ---------------- prep kernels ----------------
__global__ void prep_x_kernel(const float4* __restrict__ x, float4* __restrict__ xc) {
    size_t n = (size_t)TT * KK / 4;
    for (size_t i = blockIdx.x * (size_t)blockDim.x + threadIdx.x; i < n;
         i += (size_t)gridDim.x * blockDim.x) {
        float4 v = x[i];
        v.x = rna_tf32(v.x); v.y = rna_tf32(v.y);
        v.z = rna_tf32(v.z); v.w = rna_tf32(v.w);
        xc[i] = v;
    }
}

// W[e][k][n] -> WT[e][n][k] with rna rounding. block (32,8), grid (N/32, K/32, E)
__global__ void prep_w_kernel(const float* __restrict__ w, float* __restrict__ wt) {
    __shared__ float t[32][33];
    int e  = blockIdx.z;
    int k0 = blockIdx.y * 32;
    int n0 = blockIdx.x * 32;
    const float* we  = w  + (size_t)e * KK * NN;
    float*       wte = wt + (size_t)e * NN * KK;
    #pragma unroll
    for (int i = threadIdx.y; i < 32; i += 8)
        t[i][threadIdx.x] = we[(size_t)(k0 + i) * NN + n0 + threadIdx.x];
    __syncthreads();
    #pragma unroll
    for (int i = threadIdx.y; i < 32; i += 8)
        wte[(size_t)(n0 + i) * KK + k0 + threadIdx.x] = rna_tf32(t[threadIdx.x][i]);
}

// ---------------- main GEMM ----------------
__device__ __forceinline__ void issue_stage_load(
    const CUtensorMap* mapA, const CUtensorMap* mapB,
    uint32_t smb, int it, int s, int r0, int n0, int e0, int e1) {
    int kt = it & (KTILES - 1);
    int p  = it >> 6;                // it / KTILES
    int e  = p ? e1 : e0;
    uint32_t fb = smb + SM_FULL + s * 8;
    mbar_expect_tx(fb, STAGE_TX);
    tma_ld2d(smb + SM_A + s * A_STG, mapA, kt * BK, r0, fb);
    tma_ld2d(smb + SM_B + s * B_STG, mapB, kt * BK, e * NN + n0, fb);
}

__global__ void __launch_bounds__(128, 1) gemm_kernel(
    const __grid_constant__ CUtensorMap mapA,
    const __grid_constant__ CUtensorMap mapB,
    const float* __restrict__ bias,
    const int*   __restrict__ group_list,
    float*       __restrict__ out)
{
    extern __shared__ char smem[];
    uint32_t smb = smem_u32(smem);
    int tid = threadIdx.x;
    int lid = tid & 31, wid = tid >> 5;
    int wm = wid >> 1, wn = wid & 1;     // 2x2 warp grid, 64x64 per warp
    int g = lid >> 2, t4 = lid & 3;

    // tile mapping with GM-group swizzle for L2 reuse
    int bid = blockIdx.x;
    int group = bid / (GM * NCT);
    int inG   = bid - group * (GM * NCT);
    int tm = group * GM + (inG % GM);
    int tn = inG / GM;
    int r0 = tm * BM;
    int n0 = tn * BN;

    // experts overlapping this 128-row tile (min group size 1500 -> at most 2)
    int e0 = 0;
    while (r0 >= group_list[e0]) e0++;
    int e1 = e0;
    while (r0 + BM - 1 >= group_list[e1]) e1++;
    int npass = (e1 > e0) ? 2 : 1;
    int ee0 = group_list[e0];

    if (tid == 0) {
        #pragma unroll
        for (int s = 0; s < STAGES; s++) {
            mbar_init(smb + SM_FULL  + s * 8, 1);
            mbar_init(smb + SM_EMPTY + s * 8, 128);
        }
    }
    __syncthreads();

    int total = npass * KTILES;
    if (tid == 0) {
        #pragma unroll
        for (int i = 0; i < STAGES; i++)
            issue_stage_load(&mapA, &mapB, smb, i, i, r0, n0, e0, e1);
    }

    float C[4][8][4];
    #pragma unroll
    for (int fm = 0; fm < 4; fm++)
        #pragma unroll
        for (int fn = 0; fn < 8; fn++)
            #pragma unroll
            for (int c = 0; c < 4; c++) C[fm][fn][c] = 0.f;

    // fragment smem addressing (SW128: byte ^ ((row%8)<<4); row%8 == g for all
    // fragment rows -> per-lane constant swizzle, bank-conflict-free)
    uint32_t swz  = (uint32_t)g << 4;
    uint32_t aRow = (uint32_t)(wm * 64 + g) * 128;   // +fm*2048, +8rows = +1024
    uint32_t bRow = (uint32_t)(wn * 64 + g) * 128;   // +fn*1024

    int pf[STAGES] = {0, 0, 0, 0};
    int pe[STAGES] = {0, 0, 0, 0};

    for (int it = 0; it < total; ++it) {
        int s = it & (STAGES - 1);
        mbar_wait(smb + SM_FULL + s * 8, pf[s]); pf[s] ^= 1;

        uint32_t As = smb + SM_A + s * A_STG + aRow;
        uint32_t Bs = smb + SM_B + s * B_STG + bRow;

        #pragma unroll
        for (int ks = 0; ks < 4; ++ks) {
            uint32_t cb0 = ((uint32_t)(ks * 32 + t4 * 4)      ) ^ swz;
            uint32_t cb1 = ((uint32_t)(ks * 32 + t4 * 4 + 16) ) ^ swz;
            uint32_t a[4][4];
            #pragma unroll
            for (int fm = 0; fm < 4; ++fm) {
                uint32_t r = As + fm * 2048;
                a[fm][0] = lds32(r + cb0);
                a[fm][1] = lds32(r + 1024 + cb0);
                a[fm][2] = lds32(r + cb1);
                a[fm][3] = lds32(r + 1024 + cb1);
            }
            uint32_t b[8][2];
            #pragma unroll
            for (int fn = 0; fn < 8; ++fn) {
                uint32_t r = Bs + fn * 1024;
                b[fn][0] = lds32(r + cb0);
                b[fn][1] = lds32(r + cb1);
            }
            #pragma unroll
            for (int fm = 0; fm < 4; ++fm)
                #pragma unroll
                for (int fn = 0; fn < 8; ++fn)
                    mma8(C[fm][fn], a[fm], b[fn]);
        }

        mbar_arrive(smb + SM_EMPTY + s * 8);
        if (tid == 0 && it + STAGES < total) {
            mbar_wait(smb + SM_EMPTY + s * 8, pe[s]); pe[s] ^= 1;
            issue_stage_load(&mapA, &mapB, smb, it + STAGES, s, r0, n0, e0, e1);
        }

        if ((it & (KTILES - 1)) == KTILES - 1) {
            // ---------------- epilogue for pass p ----------------
            int p = it >> 6;
            int e = p ? e1 : e0;
            const float* bptr = bias + (size_t)e * NN + n0 + wn * 64 + t4 * 2;
            int rowbase = r0 + wm * 64 + g;
            int colbase = n0 + wn * 64 + t4 * 2;
            #pragma unroll
            for (int fn = 0; fn < 8; ++fn) {
                float2 bv = *reinterpret_cast<const float2*>(bptr + fn * 8);
                int col = colbase + fn * 8;
                #pragma unroll
                for (int fm = 0; fm < 4; ++fm) {
                    int row0 = rowbase + fm * 16;
                    int row1 = row0 + 8;
                    bool s0 = (npass == 1) || (p == 0 ? (row0 < ee0) : (row0 >= ee0));
                    bool s1 = (npass == 1) || (p == 0 ? (row1 < ee0) : (row1 >= ee0));
                    if (s0) {
                        float2 v; v.x = C[fm][fn][0] + bv.x; v.y = C[fm][fn][1] + bv.y;
                        *reinterpret_cast<float2*>(out + (size_t)row0 * NN + col) = v;
                    }
                    if (s1) {
                        float2 v; v.x = C[fm][fn][2] + bv.x; v.y = C[fm][fn][3] + bv.y;
                        *reinterpret_cast<float2*>(out + (size_t)row1 * NN + col) = v;
                    }
                }
            }
            if (p + 1 < npass) {
                #pragma unroll
                for (int fm = 0; fm < 4; fm++)
                    #pragma unroll
                    for (int fn = 0; fn < 8; fn++)
                        #pragma unroll
                        for (int c = 0; c < 4; c++) C[fm][fn][c] = 0.f;
            }
        }
    }
}

// ---------------- host ----------------
typedef CUresult (*PFN_tmapEncode)(
    CUtensorMap*, CUtensorMapDataType, cuuint32_t, void*,
    const cuuint64_t*, const cuuint64_t*, const cuuint32_t*, const cuuint32_t*,
    CUtensorMapInterleave, CUtensorMapSwizzle, CUtensorMapL2promotion,
    CUtensorMapFloatOOBfill);

extern "C" void kernel_launch(void* const* d_in, const int* in_sizes, int n_in,
                              void* d_out, int out_size) {
    const float* x    = (const float*)d_in[0];
    const float* w    = (const float*)d_in[1];
    const float* bias = (const float*)d_in[2];
    const int*   gl   = (const int*)d_in[3];
    float*       out  = (float*)d_out;
    (void)in_sizes; (void)n_in; (void)out_size;

    void* pxc = nullptr;
    void* pwt = nullptr;
    cudaGetSymbolAddress(&pxc, g_xc);
    cudaGetSymbolAddress(&pwt, g_wt);

    // operand prep: rna-round to tf32 (+ transpose W to [E][N][K])
    prep_x_kernel<<<8192, 256>>>((const float4*)x, (float4*)pxc);
    dim3 tb(32, 8), tg(NN / 32, KK / 32, EE);
    prep_w_kernel<<<tg, tb>>>(w, (float*)pwt);

    // TMA descriptors via driver entry point (no -lcuda needed)
    PFN_tmapEncode enc = nullptr;
    cudaDriverEntryPointQueryResult qr;
    cudaGetDriverEntryPoint("cuTensorMapEncodeTiled", (void**)&enc,
                            cudaEnableDefault, &qr);

    CUtensorMap mapA, mapB;
    {
        cuuint64_t dims[2]    = {KK, TT};
        cuuint64_t strides[1] = {KK * sizeof(float)};
        cuuint32_t box[2]     = {BK, BM};            // 128 B x 128 rows
        cuuint32_t es[2]      = {1, 1};
        enc(&mapA, CU_TENSOR_MAP_DATA_TYPE_FLOAT32, 2, pxc,
            dims, strides, box, es,
            CU_TENSOR_MAP_INTERLEAVE_NONE, CU_TENSOR_MAP_SWIZZLE_128B,
            CU_TENSOR_MAP_L2_PROMOTION_L2_128B, CU_TENSOR_MAP_FLOAT_OOB_FILL_NONE);
    }
    {
        cuuint64_t dims[2]    = {KK, (cuuint64_t)EE * NN};
        cuuint64_t strides[1] = {KK * sizeof(float)};
        cuuint32_t box[2]     = {BK, BN};            // 128 B x 128 rows
        cuuint32_t es[2]      = {1, 1};
        enc(&mapB, CU_TENSOR_MAP_DATA_TYPE_FLOAT32, 2, pwt,
            dims, strides, box, es,
            CU_TENSOR_MAP_INTERLEAVE_NONE, CU_TENSOR_MAP_SWIZZLE_128B,
            CU_TENSOR_MAP_L2_PROMOTION_L2_128B, CU_TENSOR_MAP_FLOAT_OOB_FILL_NONE);
    }

    cudaFuncSetAttribute(gemm_kernel,
                         cudaFuncAttributeMaxDynamicSharedMemorySize, SMEM_TOTAL);
    gemm_kernel<<<MT * NCT, 128, SMEM_TOTAL>>>(mapA, mapB, bias, gl, out);
}

// round 17
// speedup vs baseline: 1.2356x; 1.2356x over previous
#include <cuda_runtime.h>
#include <cuda.h>
#include <cstdint>
#include <cstddef>

// ---------------- problem constants ----------------
#define TT 16384
#define KK 2048
#define NN 8192
#define EE 8

static constexpr int BM = 128;
static constexpr int BN = 256;
static constexpr int BK = 32;                  // floats per stage row chunk = 128 bytes
static constexpr int STAGES = 4;
static constexpr int KTILES = KK / BK;         // 64

static constexpr int A_STG = BM * 128;         // 16384 B
static constexpr int B_STG = BN * 128;         // 32768 B
static constexpr int SM_FULL  = 0;             // 4 x 8B mbarriers
static constexpr int SM_EMPTY = SM_FULL + STAGES * 8;
static constexpr int SM_A = 1024;
static constexpr int SM_B = SM_A + STAGES * A_STG;         // 66560
static constexpr int SMEM_TOTAL = SM_B + STAGES * B_STG;   // 197632
static constexpr uint32_t STAGE_TX = (uint32_t)(A_STG + B_STG);

static constexpr int NCT = NN / BN;   // 32 col tiles
static constexpr int MT  = TT / BM;   // 128 row tiles
static constexpr int GM  = 16;        // m-tile group for L2 locality
static constexpr int NTHREADS = 256;  // 8 warps: 2 (M) x 4 (N), 64x64 per warp

// ---------------- scratch: tf32-rounded operands ----------------
__device__ float g_xc[(size_t)TT * KK];            // [T][K]
__device__ float g_wt[(size_t)EE * NN * KK];       // [E][N][K]

// ---------------- PTX helpers (base sm_103-safe: no tcgen05) ----------------
__device__ __forceinline__ uint32_t smem_u32(const void* p) {
    uint32_t a;
    asm("{ .reg .u64 t; cvta.to.shared.u64 t, %1; cvt.u32.u64 %0, t; }" : "=r"(a) : "l"(p));
    return a;
}
__device__ __forceinline__ float rna_tf32(float f) {
    uint32_t u; asm("cvt.rna.tf32.f32 %0, %1;" : "=r"(u) : "f"(f));
    return __uint_as_float(u);
}
__device__ __forceinline__ void mbar_init(uint32_t m, uint32_t cnt) {
    asm volatile("mbarrier.init.shared.b64 [%0], %1;" :: "r"(m), "r"(cnt) : "memory");
}
__device__ __forceinline__ void mbar_expect_tx(uint32_t m, uint32_t bytes) {
    asm volatile("mbarrier.arrive.expect_tx.shared.b64 _, [%0], %1;" :: "r"(m), "r"(bytes) : "memory");
}
__device__ __forceinline__ void mbar_arrive(uint32_t m) {
    asm volatile("mbarrier.arrive.shared.b64 _, [%0];" :: "r"(m) : "memory");
}
__device__ __forceinline__ void mbar_wait(uint32_t m, uint32_t parity) {
    asm volatile(
        "{\n\t.reg .pred P;\n\t"
        "WL_%=:\n\t"
        "mbarrier.try_wait.parity.shared.b64 P, [%0], %1, 0x989680;\n\t"
        "@!P bra WL_%=;\n\t}"
        :: "r"(m), "r"(parity) : "memory");
}
__device__ __forceinline__ void tma_ld2d(uint32_t dst, const CUtensorMap* map,
                                         int cx, int cy, uint32_t mbar) {
    asm volatile(
        "cp.async.bulk.tensor.2d.shared::cta.global.tile.mbarrier::complete_tx::bytes "
        "[%0], [%1, {%2, %3}], [%4];"
        :: "r"(dst), "l"(map), "r"(cx), "r"(cy), "r"(mbar) : "memory");
}
__device__ __forceinline__ uint32_t lds32(uint32_t addr) {
    uint32_t v;
    asm volatile("ld.shared.b32 %0, [%1];" : "=r"(v) : "r"(addr));
    return v;
}
// D += A*B : m16n8k8 tf32 (base-target instruction, sm_80+)
__device__ __forceinline__ void mma8(float c[4], const uint32_t a[4], const uint32_t b[2]) {
    asm volatile(
        "mma.sync.aligned.m16n8k8.row.col.f32.tf32.tf32.f32 "
        "{%0,%1,%2,%3}, {%4,%5,%6,%7}, {%8,%9}, {%0,%1,%2,%3};"
        : "+f"(c[0]), "+f"(c[1]), "+f"(c[2]), "+f"(c[3])
        : "r"(a[0]), "r"(a[1]), "r"(a[2]), "r"(a[3]), "r"(b[0]), "r"(b[1]));
}

// ---------------- prep kernels ----------------
__global__ void prep_x_kernel(const float4* __restrict__ x, float4* __restrict__ xc) {
    size_t n = (size_t)TT * KK / 4;
    for (size_t i = blockIdx.x * (size_t)blockDim.x + threadIdx.x; i < n;
         i += (size_t)gridDim.x * blockDim.x) {
        float4 v = x[i];
        v.x = rna_tf32(v.x); v.y = rna_tf32(v.y);
        v.z = rna_tf32(v.z); v.w = rna_tf32(v.w);
        xc[i] = v;
    }
}

// W[e][k][n] -> WT[e][n][k] with rna rounding. block (32,8), grid (N/32, K/32, E)
__global__ void prep_w_kernel(const float* __restrict__ w, float* __restrict__ wt) {
    __shared__ float t[32][33];
    int e  = blockIdx.z;
    int k0 = blockIdx.y * 32;
    int n0 = blockIdx.x * 32;
    const float* we  = w  + (size_t)e * KK * NN;
    float*       wte = wt + (size_t)e * NN * KK;
    #pragma unroll
    for (int i = threadIdx.y; i < 32; i += 8)
        t[i][threadIdx.x] = we[(size_t)(k0 + i) * NN + n0 + threadIdx.x];
    __syncthreads();
    #pragma unroll
    for (int i = threadIdx.y; i < 32; i += 8)
        wte[(size_t)(n0 + i) * KK + k0 + threadIdx.x] = rna_tf32(t[threadIdx.x][i]);
}

// ---------------- main GEMM ----------------
__device__ __forceinline__ void issue_stage_load(
    const CUtensorMap* mapA, const CUtensorMap* mapB,
    uint32_t smb, int it, int s, int r0, int n0, int e0, int e1) {
    int kt = it & (KTILES - 1);
    int p  = it >> 6;                // it / KTILES
    int e  = p ? e1 : e0;
    uint32_t fb = smb + SM_FULL + s * 8;
    mbar_expect_tx(fb, STAGE_TX);
    tma_ld2d(smb + SM_A + s * A_STG, mapA, kt * BK, r0, fb);
    tma_ld2d(smb + SM_B + s * B_STG, mapB, kt * BK, e * NN + n0, fb);
}

__global__ void __launch_bounds__(NTHREADS, 1) gemm_kernel(
    const __grid_constant__ CUtensorMap mapA,
    const __grid_constant__ CUtensorMap mapB,
    const float* __restrict__ bias,
    const int*   __restrict__ group_list,
    float*       __restrict__ out)
{
    extern __shared__ char smem[];
    uint32_t smb = smem_u32(smem);
    int tid = threadIdx.x;
    int lid = tid & 31, wid = tid >> 5;
    int wm = wid >> 2, wn = wid & 3;     // 2x4 warp grid, 64x64 per warp
    int g = lid >> 2, t4 = lid & 3;

    // tile mapping with GM-group swizzle for L2 reuse
    int bid = blockIdx.x;
    int group = bid / (GM * NCT);
    int inG   = bid - group * (GM * NCT);
    int tm = group * GM + (inG % GM);
    int tn = inG / GM;
    int r0 = tm * BM;
    int n0 = tn * BN;

    // experts overlapping this 128-row tile (min group size 1500 -> at most 2)
    int e0 = 0;
    while (r0 >= group_list[e0]) e0++;
    int e1 = e0;
    while (r0 + BM - 1 >= group_list[e1]) e1++;
    int npass = (e1 > e0) ? 2 : 1;
    int ee0 = group_list[e0];

    if (tid == 0) {
        #pragma unroll
        for (int s = 0; s < STAGES; s++) {
            mbar_init(smb + SM_FULL  + s * 8, 1);
            mbar_init(smb + SM_EMPTY + s * 8, NTHREADS);
        }
    }
    __syncthreads();

    int total = npass * KTILES;
    if (tid == 0) {
        #pragma unroll
        for (int i = 0; i < STAGES; i++)
            issue_stage_load(&mapA, &mapB, smb, i, i, r0, n0, e0, e1);
    }

    float C[4][8][4];
    #pragma unroll
    for (int fm = 0; fm < 4; fm++)
        #pragma unroll
        for (int fn = 0; fn < 8; fn++)
            #pragma unroll
            for (int c = 0; c < 4; c++) C[fm][fn][c] = 0.f;

    // fragment smem addressing (SW128: byte ^ ((row%8)<<4); row%8 == g for all
    // fragment rows -> per-lane constant swizzle, bank-conflict-free)
    uint32_t swz  = (uint32_t)g << 4;
    uint32_t aRow = (uint32_t)(wm * 64 + g) * 128;   // +fm*2048, +8rows = +1024
    uint32_t bRow = (uint32_t)(wn * 64 + g) * 128;   // +fn*1024

    int pf[STAGES] = {0, 0, 0, 0};
    int pe[STAGES] = {0, 0, 0, 0};

    for (int it = 0; it < total; ++it) {
        int s = it & (STAGES - 1);
        mbar_wait(smb + SM_FULL + s * 8, pf[s]); pf[s] ^= 1;

        uint32_t As = smb + SM_A + s * A_STG + aRow;
        uint32_t Bs = smb + SM_B + s * B_STG + bRow;

        #pragma unroll
        for (int ks = 0; ks < 4; ++ks) {
            uint32_t cb0 = ((uint32_t)(ks * 32 + t4 * 4)     ) ^ swz;
            uint32_t cb1 = ((uint32_t)(ks * 32 + t4 * 4 + 16)) ^ swz;
            uint32_t a[4][4];
            #pragma unroll
            for (int fm = 0; fm < 4; ++fm) {
                uint32_t r = As + fm * 2048;
                a[fm][0] = lds32(r + cb0);
                a[fm][1] = lds32(r + 1024 + cb0);
                a[fm][2] = lds32(r + cb1);
                a[fm][3] = lds32(r + 1024 + cb1);
            }
            uint32_t b[8][2];
            #pragma unroll
            for (int fn = 0; fn < 8; ++fn) {
                uint32_t r = Bs + fn * 1024;
                b[fn][0] = lds32(r + cb0);
                b[fn][1] = lds32(r + cb1);
            }
            #pragma unroll
            for (int fm = 0; fm < 4; ++fm)
                #pragma unroll
                for (int fn = 0; fn < 8; ++fn)
                    mma8(C[fm][fn], a[fm], b[fn]);
        }

        mbar_arrive(smb + SM_EMPTY + s * 8);
        if (tid == 0 && it + STAGES < total) {
            mbar_wait(smb + SM_EMPTY + s * 8, pe[s]); pe[s] ^= 1;
            issue_stage_load(&mapA, &mapB, smb, it + STAGES, s, r0, n0, e0, e1);
        }

        if ((it & (KTILES - 1)) == KTILES - 1) {
            // ---------------- epilogue for pass p ----------------
            int p = it >> 6;
            int e = p ? e1 : e0;
            const float* bptr = bias + (size_t)e * NN + n0 + wn * 64 + t4 * 2;
            int rowbase = r0 + wm * 64 + g;
            int colbase = n0 + wn * 64 + t4 * 2;
            #pragma unroll
            for (int fn = 0; fn < 8; ++fn) {
                float2 bv = *reinterpret_cast<const float2*>(bptr + fn * 8);
                int col = colbase + fn * 8;
                #pragma unroll
                for (int fm = 0; fm < 4; ++fm) {
                    int row0 = rowbase + fm * 16;
                    int row1 = row0 + 8;
                    bool s0 = (npass == 1) || (p == 0 ? (row0 < ee0) : (row0 >= ee0));
                    bool s1 = (npass == 1) || (p == 0 ? (row1 < ee0) : (row1 >= ee0));
                    if (s0) {
                        float2 v; v.x = C[fm][fn][0] + bv.x; v.y = C[fm][fn][1] + bv.y;
                        *reinterpret_cast<float2*>(out + (size_t)row0 * NN + col) = v;
                    }
                    if (s1) {
                        float2 v; v.x = C[fm][fn][2] + bv.x; v.y = C[fm][fn][3] + bv.y;
                        *reinterpret_cast<float2*>(out + (size_t)row1 * NN + col) = v;
                    }
                }
            }
            if (p + 1 < npass) {
                #pragma unroll
                for (int fm = 0; fm < 4; fm++)
                    #pragma unroll
                    for (int fn = 0; fn < 8; fn++)
                        #pragma unroll
                        for (int c = 0; c < 4; c++) C[fm][fn][c] = 0.f;
            }
        }
    }
}

// ---------------- host ----------------
typedef CUresult (*PFN_tmapEncode)(
    CUtensorMap*, CUtensorMapDataType, cuuint32_t, void*,
    const cuuint64_t*, const cuuint64_t*, const cuuint32_t*, const cuuint32_t*,
    CUtensorMapInterleave, CUtensorMapSwizzle, CUtensorMapL2promotion,
    CUtensorMapFloatOOBfill);

extern "C" void kernel_launch(void* const* d_in, const int* in_sizes, int n_in,
                              void* d_out, int out_size) {
    const float* x    = (const float*)d_in[0];
    const float* w    = (const float*)d_in[1];
    const float* bias = (const float*)d_in[2];
    const int*   gl   = (const int*)d_in[3];
    float*       out  = (float*)d_out;
    (void)in_sizes; (void)n_in; (void)out_size;

    void* pxc = nullptr;
    void* pwt = nullptr;
    cudaGetSymbolAddress(&pxc, g_xc);
    cudaGetSymbolAddress(&pwt, g_wt);

    // operand prep: rna-round to tf32 (+ transpose W to [E][N][K])
    prep_x_kernel<<<8192, 256>>>((const float4*)x, (float4*)pxc);
    dim3 tb(32, 8), tg(NN / 32, KK / 32, EE);
    prep_w_kernel<<<tg, tb>>>(w, (float*)pwt);

    // TMA descriptors via driver entry point (no -lcuda needed)
    PFN_tmapEncode enc = nullptr;
    cudaDriverEntryPointQueryResult qr;
    cudaGetDriverEntryPoint("cuTensorMapEncodeTiled", (void**)&enc,
                            cudaEnableDefault, &qr);

    CUtensorMap mapA, mapB;
    {
        cuuint64_t dims[2]    = {KK, TT};
        cuuint64_t strides[1] = {KK * sizeof(float)};
        cuuint32_t box[2]     = {BK, BM};            // 128 B x 128 rows
        cuuint32_t es[2]      = {1, 1};
        enc(&mapA, CU_TENSOR_MAP_DATA_TYPE_FLOAT32, 2, pxc,
            dims, strides, box, es,
            CU_TENSOR_MAP_INTERLEAVE_NONE, CU_TENSOR_MAP_SWIZZLE_128B,
            CU_TENSOR_MAP_L2_PROMOTION_L2_128B, CU_TENSOR_MAP_FLOAT_OOB_FILL_NONE);
    }
    {
        cuuint64_t dims[2]    = {KK, (cuuint64_t)EE * NN};
        cuuint64_t strides[1] = {KK * sizeof(float)};
        cuuint32_t box[2]     = {BK, BN};            // 128 B x 256 rows
        cuuint32_t es[2]      = {1, 1};
        enc(&mapB, CU_TENSOR_MAP_DATA_TYPE_FLOAT32, 2, pwt,
            dims, strides, box, es,
            CU_TENSOR_MAP_INTERLEAVE_NONE, CU_TENSOR_MAP_SWIZZLE_128B,
            CU_TENSOR_MAP_L2_PROMOTION_L2_128B, CU_TENSOR_MAP_FLOAT_OOB_FILL_NONE);
    }

    cudaFuncSetAttribute(gemm_kernel,
                         cudaFuncAttributeMaxDynamicSharedMemorySize, SMEM_TOTAL);
    gemm_kernel<<<MT * NCT, NTHREADS, SMEM_TOTAL>>>(mapA, mapB, bias, gl, out);
}